// round 1
// baseline (speedup 1.0000x reference)
#include <cuda_runtime.h>

#define BB 256
#define PP 1000
#define UU 768
#define EE 128

// Folded weight matrices (computed once per launch by precompute_kernel).
__device__ float g_Ck[3][EE], g_bk[EE];
__device__ float g_Cv[3][EE], g_bv[EE];
__device__ float g_Cq[3][EE], g_bq[EE], g_wql[EE];

// Ck = W_embed @ Wk (3x128), bk = b_embed @ Wk, etc.
// Wq is (E+1, E): rows 0..127 act on enc, row 128 acts on load.
__global__ void precompute_kernel(const float* __restrict__ W_embed,
                                  const float* __restrict__ b_embed,
                                  const float* __restrict__ Wq,
                                  const float* __restrict__ Wk,
                                  const float* __restrict__ Wv) {
    int e = threadIdx.x;  // 0..127
    float ck0 = 0.f, ck1 = 0.f, ck2 = 0.f, bk = 0.f;
    float cv0 = 0.f, cv1 = 0.f, cv2 = 0.f, bv = 0.f;
    float cq0 = 0.f, cq1 = 0.f, cq2 = 0.f, bq = 0.f;
    for (int j = 0; j < EE; j++) {
        float w0 = W_embed[j];
        float w1 = W_embed[EE + j];
        float w2 = W_embed[2 * EE + j];
        float bb = b_embed[j];
        float wk = Wk[j * EE + e];
        float wv = Wv[j * EE + e];
        float wq = Wq[j * EE + e];
        ck0 = fmaf(w0, wk, ck0); ck1 = fmaf(w1, wk, ck1);
        ck2 = fmaf(w2, wk, ck2); bk  = fmaf(bb, wk, bk);
        cv0 = fmaf(w0, wv, cv0); cv1 = fmaf(w1, wv, cv1);
        cv2 = fmaf(w2, wv, cv2); bv  = fmaf(bb, wv, bv);
        cq0 = fmaf(w0, wq, cq0); cq1 = fmaf(w1, wq, cq1);
        cq2 = fmaf(w2, wq, cq2); bq  = fmaf(bb, wq, bq);
    }
    g_Ck[0][e] = ck0; g_Ck[1][e] = ck1; g_Ck[2][e] = ck2; g_bk[e] = bk;
    g_Cv[0][e] = cv0; g_Cv[1][e] = cv1; g_Cv[2][e] = cv2; g_bv[e] = bv;
    g_Cq[0][e] = cq0; g_Cq[1][e] = cq1; g_Cq[2][e] = cq2; g_bq[e] = bq;
    g_wql[e] = Wq[EE * EE + e];
}

__global__ __launch_bounds__(256, 2)
void cvrp_main_kernel(const float* __restrict__ depot_xy,
                      const float* __restrict__ node_xy,
                      const float* __restrict__ node_demand,
                      const float* __restrict__ load_in,
                      const float* __restrict__ cur_dist,
                      const float* __restrict__ ninf_mask,
                      const float* __restrict__ log_scale,
                      const float* __restrict__ W_embed,
                      const float* __restrict__ b_embed,
                      const float* __restrict__ alpha_attn,
                      const float* __restrict__ alpha_com,
                      const int* __restrict__ current_node,
                      const int* __restrict__ uvi,
                      float* __restrict__ out) {
    __shared__ float xs[UU], ys[UU], ds[UU], ws[UU], bias_s[UU], nfs[UU], ts[UU];
    __shared__ int   sidx[UU];
    __shared__ float numden[2 * EE];
    __shared__ float red[256];
    __shared__ int   redi[256];
    __shared__ float s_cn[3];
    __shared__ float s_A[4];

    const int b = blockIdx.x;
    const int tid = threadIdx.x;

    const float ls = log_scale[0];
    const float lsaa = -ls * alpha_attn[0];
    const float lsac = -ls * alpha_com[0];
    const float loadb = load_in[b];

    // Zero this batch's output row (harness poisons d_out with 0xAA).
    for (int j = tid; j < PP + 1; j += 256) out[b * (PP + 1) + j] = 0.f;

    // Stage current-node features.
    if (tid == 0) {
        int cn = current_node[b];
        if (cn == 0) {
            s_cn[0] = depot_xy[2 * b];
            s_cn[1] = depot_xy[2 * b + 1];
            s_cn[2] = 0.f;
        } else {
            long o = (long)b * PP + (cn - 1);
            s_cn[0] = node_xy[2 * o];
            s_cn[1] = node_xy[2 * o + 1];
            s_cn[2] = node_demand[o];
        }
    }

    // Stage gathered (x, y, demand), attention weight w, com bias, ninf, index.
    for (int u = tid; u < UU; u += 256) {
        int idx = uvi[b * UU + u];
        sidx[u] = idx;
        float x, y, d;
        if (idx == 0) {
            x = depot_xy[2 * b];
            y = depot_xy[2 * b + 1];
            d = 0.f;
        } else {
            long o = (long)b * PP + (idx - 1);
            x = node_xy[2 * o];
            y = node_xy[2 * o + 1];
            d = node_demand[o];
        }
        xs[u] = x; ys[u] = y; ds[u] = d;
        float dist = cur_dist[b * UU + u];
        float nf = ninf_mask[b * UU + u];
        ws[u] = expf(fmaf(lsaa, dist, nf));   // w = exp(-ls*aa*dist + ninf)
        bias_s[u] = lsac * dist;              // bias_com
        nfs[u] = nf;
    }
    __syncthreads();

    // Phase 1: num[e] = sum_u w*exp(k)*v, den[e] = sum_u w*exp(k).
    // Thread layout: e = tid&127, two half-blocks split the u range.
    const int e = tid & (EE - 1);
    const int h = tid >> 7;
    const float ck0 = g_Ck[0][e], ck1 = g_Ck[1][e], ck2 = g_Ck[2][e], bk = g_bk[e];
    const float cv0 = g_Cv[0][e], cv1 = g_Cv[1][e], cv2 = g_Cv[2][e], bv = g_bv[e];
    float num = 0.f, den = 0.f;
    const int u0 = h * (UU / 2);
#pragma unroll 4
    for (int u = u0; u < u0 + UU / 2; u++) {
        float x = xs[u], y = ys[u], d = ds[u], w = ws[u];
        float k = fmaf(x, ck0, fmaf(y, ck1, fmaf(d, ck2, bk)));
        float v = fmaf(x, cv0, fmaf(y, cv1, fmaf(d, cv2, bv)));
        float t = w * expf(k);
        den += t;
        num = fmaf(t, v, num);
    }
    if (h == 1) { numden[e] = num; numden[EE + e] = den; }
    __syncthreads();

    // Half tid<128 finalizes num/den, computes q, aafm, and the 4 folded
    // epilogue scalars p = aafm * {W_embed rows, b_embed}.
    float p0 = 0.f, p1 = 0.f, p2 = 0.f, p3 = 0.f;
    if (h == 0) {
        num += numden[e];
        den += numden[EE + e];
        float cq0 = g_Cq[0][e], cq1 = g_Cq[1][e], cq2 = g_Cq[2][e];
        float bq = g_bq[e], wql = g_wql[e];
        float q = fmaf(s_cn[0], cq0, fmaf(s_cn[1], cq1, fmaf(s_cn[2], cq2, bq)))
                + loadb * wql;
        float sig = 1.f / (1.f + expf(-q));
        float aafm = sig * (num / den);
        p0 = aafm * W_embed[e];
        p1 = aafm * W_embed[EE + e];
        p2 = aafm * W_embed[2 * EE + e];
        p3 = aafm * b_embed[e];
    }
    __syncthreads();

    // Block-sum the 4 scalars A0..A2, Ab.
    float ps[4] = {p0, p1, p2, p3};
#pragma unroll
    for (int i = 0; i < 4; i++) {
        red[tid] = ps[i];
        __syncthreads();
        for (int s = 128; s > 0; s >>= 1) {
            if (tid < s) red[tid] += red[tid + s];
            __syncthreads();
        }
        if (tid == 0) s_A[i] = red[0];
        __syncthreads();
    }
    const float A0 = s_A[0], A1 = s_A[1], A2 = s_A[2], Ab = s_A[3];

    // Phase 2: score_u = (aafm . sk_u)/sqrt(E) + bias_com_u, then
    // t_u = CLIP*tanh(score_u) + ninf_u.
    const float INV_SQRT_E = 0.08838834764831845f;  // 1/sqrt(128)
    for (int u = tid; u < UU; u += 256) {
        float sc = fmaf(xs[u], A0, fmaf(ys[u], A1, fmaf(ds[u], A2, Ab))) * INV_SQRT_E
                 + bias_s[u];
        ts[u] = fmaf(10.f, tanhf(sc), nfs[u]);
    }
    __syncthreads();

    // Softmax max + first-index argmax over 768.
    float lm = -3.402823466e38f;
    int li = 0x7fffffff;
    for (int u = tid; u < UU; u += 256) {
        float t = ts[u];
        if (t > lm) { lm = t; li = u; }   // ascending u -> first occurrence
    }
    red[tid] = lm;
    redi[tid] = li;
    __syncthreads();
    for (int s = 128; s > 0; s >>= 1) {
        if (tid < s) {
            float o = red[tid + s];
            int oi = redi[tid + s];
            if (o > red[tid] || (o == red[tid] && oi < redi[tid])) {
                red[tid] = o;
                redi[tid] = oi;
            }
        }
        __syncthreads();
    }
    const float mx = red[0];
    const int amax = redi[0];
    __syncthreads();   // red[] gets reused below

    // Softmax sum.
    float lsum = 0.f;
    for (int u = tid; u < UU; u += 256) lsum += expf(ts[u] - mx);
    red[tid] = lsum;
    __syncthreads();
    for (int s = 128; s > 0; s >>= 1) {
        if (tid < s) red[tid] += red[tid + s];
        __syncthreads();
    }
    const float inv = 1.f / red[0];

    // Scatter probs into upper_scores, emit true_selected + selected_score.
    for (int u = tid; u < UU; u += 256)
        out[b * (PP + 1) + sidx[u]] = expf(ts[u] - mx) * inv;
    if (tid == 0) {
        out[BB * (PP + 1) + b] = (float)sidx[amax];                 // true_selected
        out[BB * (PP + 1) + BB + b] = expf(ts[amax] - mx) * inv;    // selected_score
    }
}

extern "C" void kernel_launch(void* const* d_in, const int* in_sizes, int n_in,
                              void* d_out, int out_size) {
    (void)in_sizes; (void)n_in; (void)out_size;
    const float* depot_xy    = (const float*)d_in[0];
    const float* node_xy     = (const float*)d_in[1];
    const float* node_demand = (const float*)d_in[2];
    const float* load_in     = (const float*)d_in[3];
    const float* cur_dist    = (const float*)d_in[4];
    const float* ninf_mask   = (const float*)d_in[5];
    const float* log_scale   = (const float*)d_in[6];
    const float* W_embed     = (const float*)d_in[7];
    const float* b_embed     = (const float*)d_in[8];
    const float* Wq          = (const float*)d_in[9];
    const float* Wk          = (const float*)d_in[10];
    const float* Wv          = (const float*)d_in[11];
    const float* alpha_attn  = (const float*)d_in[12];
    const float* alpha_com   = (const float*)d_in[13];
    const int*   current_node = (const int*)d_in[14];
    const int*   uvi          = (const int*)d_in[15];
    float* out = (float*)d_out;

    precompute_kernel<<<1, 128>>>(W_embed, b_embed, Wq, Wk, Wv);
    cvrp_main_kernel<<<BB, 256>>>(depot_xy, node_xy, node_demand, load_in,
                                  cur_dist, ninf_mask, log_scale, W_embed,
                                  b_embed, alpha_attn, alpha_com,
                                  current_node, uvi, out);
}

// round 2
// speedup vs baseline: 1.5961x; 1.5961x over previous
#include <cuda_runtime.h>

#define BB 256
#define PP 1000
#define UU 768
#define EE 128
#define LOG2E 1.4426950408889634f

// Folded weight matrices. Ck/bk are pre-scaled by LOG2E so exp(k) == ex2(k2).
__device__ float g_Ck[3][EE], g_bk[EE];
__device__ float g_Cv[3][EE], g_bv[EE];
__device__ float g_Cq[3][EE], g_bq[EE], g_wql[EE];

__device__ __forceinline__ float ex2(float x) {
    float r;
    asm("ex2.approx.f32 %0, %1;" : "=f"(r) : "f"(x));
    return r;
}

// Ck = W_embed @ Wk (3x128), bk = b_embed @ Wk, etc.  512 threads:
// e = tid&127, j-chunk = tid>>7 (32 j's each), smem combine.
__global__ __launch_bounds__(512)
void precompute_kernel(const float* __restrict__ W_embed,
                       const float* __restrict__ b_embed,
                       const float* __restrict__ Wq,
                       const float* __restrict__ Wk,
                       const float* __restrict__ Wv) {
    __shared__ float part[4][12][EE];
    const int tid = threadIdx.x;
    const int e = tid & (EE - 1);
    const int jc = tid >> 7;
    float a[12];
#pragma unroll
    for (int i = 0; i < 12; i++) a[i] = 0.f;
    const int j0 = jc * 32;
#pragma unroll 4
    for (int j = j0; j < j0 + 32; j++) {
        float w0 = W_embed[j];
        float w1 = W_embed[EE + j];
        float w2 = W_embed[2 * EE + j];
        float bb = b_embed[j];
        float wk = Wk[j * EE + e];
        float wv = Wv[j * EE + e];
        float wq = Wq[j * EE + e];
        a[0] = fmaf(w0, wk, a[0]); a[1] = fmaf(w1, wk, a[1]);
        a[2] = fmaf(w2, wk, a[2]); a[3] = fmaf(bb, wk, a[3]);
        a[4] = fmaf(w0, wv, a[4]); a[5] = fmaf(w1, wv, a[5]);
        a[6] = fmaf(w2, wv, a[6]); a[7] = fmaf(bb, wv, a[7]);
        a[8] = fmaf(w0, wq, a[8]); a[9] = fmaf(w1, wq, a[9]);
        a[10] = fmaf(w2, wq, a[10]); a[11] = fmaf(bb, wq, a[11]);
    }
#pragma unroll
    for (int i = 0; i < 12; i++) part[jc][i][e] = a[i];
    __syncthreads();
    if (tid < EE) {
        float s[12];
#pragma unroll
        for (int i = 0; i < 12; i++)
            s[i] = part[0][i][e] + part[1][i][e] + part[2][i][e] + part[3][i][e];
        // K coefficients pre-scaled into base-2 exponent space.
        g_Ck[0][e] = s[0] * LOG2E; g_Ck[1][e] = s[1] * LOG2E;
        g_Ck[2][e] = s[2] * LOG2E; g_bk[e] = s[3] * LOG2E;
        g_Cv[0][e] = s[4]; g_Cv[1][e] = s[5]; g_Cv[2][e] = s[6]; g_bv[e] = s[7];
        g_Cq[0][e] = s[8]; g_Cq[1][e] = s[9]; g_Cq[2][e] = s[10]; g_bq[e] = s[11];
        g_wql[e] = Wq[EE * EE + e];
    }
}

__global__ __launch_bounds__(512, 2)
void cvrp_main_kernel(const float* __restrict__ depot_xy,
                      const float* __restrict__ node_xy,
                      const float* __restrict__ node_demand,
                      const float* __restrict__ load_in,
                      const float* __restrict__ cur_dist,
                      const float* __restrict__ ninf_mask,
                      const float* __restrict__ log_scale,
                      const float* __restrict__ W_embed,
                      const float* __restrict__ b_embed,
                      const float* __restrict__ alpha_attn,
                      const float* __restrict__ alpha_com,
                      const int* __restrict__ current_node,
                      const int* __restrict__ uvi,
                      float* __restrict__ out) {
    __shared__ float4 xs4[UU];        // x, y, d, lw2 (= (lsaa*dist+nf)*LOG2E)
    __shared__ float2 bn[UU];         // bias_com, ninf
    __shared__ float  ts[UU];         // logits*LOG2E, later exp values
    __shared__ int    sidx[UU];
    __shared__ float  numden[3][2][EE];
    __shared__ float  red[32];
    __shared__ int    redi[32];
    __shared__ float  pw[4][4];
    __shared__ float  s_cn[3];
    __shared__ float  s_A[4];
    __shared__ float  s_mx, s_sum;
    __shared__ int    s_amax;

    const int b = blockIdx.x;
    const int tid = threadIdx.x;
    const int lane = tid & 31;
    const int wid = tid >> 5;

    const float ls = log_scale[0];
    const float lsaa2 = -ls * alpha_attn[0] * LOG2E;
    const float lsac = -ls * alpha_com[0];
    const float loadb = load_in[b];

    // Zero this batch's output row (harness poisons d_out).
    for (int j = tid; j < PP + 1; j += 512) out[b * (PP + 1) + j] = 0.f;

    if (tid == 0) {
        int cn = current_node[b];
        if (cn == 0) {
            float2 dp = ((const float2*)depot_xy)[b];
            s_cn[0] = dp.x; s_cn[1] = dp.y; s_cn[2] = 0.f;
        } else {
            long o = (long)b * PP + (cn - 1);
            float2 xy = ((const float2*)node_xy)[o];
            s_cn[0] = xy.x; s_cn[1] = xy.y; s_cn[2] = node_demand[o];
        }
    }

    // Gather staged features.
    for (int u = tid; u < UU; u += 512) {
        int idx = uvi[b * UU + u];
        sidx[u] = idx;
        float x, y, d;
        if (idx == 0) {
            float2 dp = ((const float2*)depot_xy)[b];
            x = dp.x; y = dp.y; d = 0.f;
        } else {
            long o = (long)b * PP + (idx - 1);
            float2 xy = ((const float2*)node_xy)[o];
            x = xy.x; y = xy.y; d = node_demand[o];
        }
        float dist = cur_dist[b * UU + u];
        float nf = ninf_mask[b * UU + u];
        float lw2 = fmaf(lsaa2, dist, nf * LOG2E);  // log2(w)
        xs4[u] = make_float4(x, y, d, lw2);
        bn[u] = make_float2(lsac * dist, nf);
    }
    __syncthreads();

    // Phase 1: num[e] = sum_u w*exp(k)*v, den[e] = sum_u w*exp(k).
    // e = tid&127; four quarter-blocks split the u range.
    const int e = tid & (EE - 1);
    const int q = tid >> 7;
    const float ck0 = g_Ck[0][e], ck1 = g_Ck[1][e], ck2 = g_Ck[2][e], bk = g_bk[e];
    const float cv0 = g_Cv[0][e], cv1 = g_Cv[1][e], cv2 = g_Cv[2][e], bv = g_bv[e];
    float num = 0.f, den = 0.f;
    const int u0 = q * (UU / 4);
#pragma unroll 4
    for (int u = u0; u < u0 + UU / 4; u++) {
        float4 f = xs4[u];
        float k2 = fmaf(f.x, ck0, fmaf(f.y, ck1, fmaf(f.z, ck2, bk))) + f.w;
        float v  = fmaf(f.x, cv0, fmaf(f.y, cv1, fmaf(f.z, cv2, bv)));
        float t = ex2(k2);
        den += t;
        num = fmaf(t, v, num);
    }
    if (q > 0) { numden[q - 1][0][e] = num; numden[q - 1][1][e] = den; }
    __syncthreads();

    // tid<128 (warps 0-3) finalizes num/den, q, aafm, and the folded
    // epilogue scalars p = aafm * {W_embed rows, b_embed}.
    float p0 = 0.f, p1 = 0.f, p2 = 0.f, p3 = 0.f;
    if (tid < EE) {
        num += numden[0][0][e] + numden[1][0][e] + numden[2][0][e];
        den += numden[0][1][e] + numden[1][1][e] + numden[2][1][e];
        float qv = fmaf(s_cn[0], g_Cq[0][e],
                  fmaf(s_cn[1], g_Cq[1][e],
                  fmaf(s_cn[2], g_Cq[2][e], g_bq[e])))
                 + loadb * g_wql[e];
        float sig = 1.f / (1.f + ex2(-qv * LOG2E));
        float aafm = sig * (num / den);
        p0 = aafm * W_embed[e];
        p1 = aafm * W_embed[EE + e];
        p2 = aafm * W_embed[2 * EE + e];
        p3 = aafm * b_embed[e];
    }
    // Warp butterfly within warps 0-3, then 4x4 combine.
    if (tid < EE) {
#pragma unroll
        for (int o = 16; o; o >>= 1) {
            p0 += __shfl_xor_sync(0xffffffffu, p0, o);
            p1 += __shfl_xor_sync(0xffffffffu, p1, o);
            p2 += __shfl_xor_sync(0xffffffffu, p2, o);
            p3 += __shfl_xor_sync(0xffffffffu, p3, o);
        }
        if (lane == 0) {
            pw[wid][0] = p0; pw[wid][1] = p1; pw[wid][2] = p2; pw[wid][3] = p3;
        }
    }
    __syncthreads();
    if (tid < 4)
        s_A[tid] = pw[0][tid] + pw[1][tid] + pw[2][tid] + pw[3][tid];
    __syncthreads();
    const float A0 = s_A[0], A1 = s_A[1], A2 = s_A[2], Ab = s_A[3];

    // Phase 2: logit2_u = (10*tanh(score_u) + nf_u) * LOG2E.
    const float INV_SQRT_E = 0.08838834764831845f;  // 1/sqrt(128)
    for (int u = tid; u < UU; u += 512) {
        float4 f = xs4[u];
        float2 bnu = bn[u];
        float sc = fmaf(f.x, A0, fmaf(f.y, A1, fmaf(f.z, A2, Ab))) * INV_SQRT_E
                 + bnu.x;
        // tanh(sc) = 1 - 2/(exp(2*sc)+1), in base 2
        float e2 = ex2(sc * (2.f * LOG2E));
        float th = 1.f - __fdividef(2.f, e2 + 1.f);
        ts[u] = (fmaf(10.f, th, bnu.y)) * LOG2E;
    }
    __syncthreads();

    // Max + first-index argmax over 768.
    float lm = -3.402823466e38f;
    int li = 0x7fffffff;
    for (int u = tid; u < UU; u += 512) {
        float t = ts[u];
        if (t > lm) { lm = t; li = u; }
    }
#pragma unroll
    for (int o = 16; o; o >>= 1) {
        float om = __shfl_xor_sync(0xffffffffu, lm, o);
        int oi = __shfl_xor_sync(0xffffffffu, li, o);
        if (om > lm || (om == lm && oi < li)) { lm = om; li = oi; }
    }
    if (lane == 0) { red[wid] = lm; redi[wid] = li; }
    __syncthreads();
    if (tid < 32) {
        float m2 = (tid < 16) ? red[tid] : -3.402823466e38f;
        int mi2 = (tid < 16) ? redi[tid] : 0x7fffffff;
#pragma unroll
        for (int o = 8; o; o >>= 1) {
            float om = __shfl_xor_sync(0xffffffffu, m2, o);
            int oi = __shfl_xor_sync(0xffffffffu, mi2, o);
            if (om > m2 || (om == m2 && oi < mi2)) { m2 = om; mi2 = oi; }
        }
        if (tid == 0) { s_mx = m2; s_amax = mi2; }
    }
    __syncthreads();
    const float mx = s_mx;

    // Softmax sum; store exp values back into ts.
    float lsum = 0.f;
    for (int u = tid; u < UU; u += 512) {
        float p = ex2(ts[u] - mx);
        ts[u] = p;
        lsum += p;
    }
#pragma unroll
    for (int o = 16; o; o >>= 1) lsum += __shfl_xor_sync(0xffffffffu, lsum, o);
    if (lane == 0) red[wid] = lsum;
    __syncthreads();
    if (tid < 32) {
        float v = (tid < 16) ? red[tid] : 0.f;
#pragma unroll
        for (int o = 8; o; o >>= 1) v += __shfl_xor_sync(0xffffffffu, v, o);
        if (tid == 0) s_sum = v;
    }
    __syncthreads();
    const float inv = 1.f / s_sum;

    // Scatter probs; emit true_selected + selected_score.
    for (int u = tid; u < UU; u += 512)
        out[b * (PP + 1) + sidx[u]] = ts[u] * inv;
    if (tid == 0) {
        int amax = s_amax;
        out[BB * (PP + 1) + b] = (float)sidx[amax];
        out[BB * (PP + 1) + BB + b] = ts[amax] * inv;
    }
}

extern "C" void kernel_launch(void* const* d_in, const int* in_sizes, int n_in,
                              void* d_out, int out_size) {
    (void)in_sizes; (void)n_in; (void)out_size;
    const float* depot_xy    = (const float*)d_in[0];
    const float* node_xy     = (const float*)d_in[1];
    const float* node_demand = (const float*)d_in[2];
    const float* load_in     = (const float*)d_in[3];
    const float* cur_dist    = (const float*)d_in[4];
    const float* ninf_mask   = (const float*)d_in[5];
    const float* log_scale   = (const float*)d_in[6];
    const float* W_embed     = (const float*)d_in[7];
    const float* b_embed     = (const float*)d_in[8];
    const float* Wq          = (const float*)d_in[9];
    const float* Wk          = (const float*)d_in[10];
    const float* Wv          = (const float*)d_in[11];
    const float* alpha_attn  = (const float*)d_in[12];
    const float* alpha_com   = (const float*)d_in[13];
    const int*   current_node = (const int*)d_in[14];
    const int*   uvi          = (const int*)d_in[15];
    float* out = (float*)d_out;

    precompute_kernel<<<1, 512>>>(W_embed, b_embed, Wq, Wk, Wv);
    cvrp_main_kernel<<<BB, 512>>>(depot_xy, node_xy, node_demand, load_in,
                                  cur_dist, ninf_mask, log_scale, W_embed,
                                  b_embed, alpha_attn, alpha_com,
                                  current_node, uvi, out);
}

// round 3
// speedup vs baseline: 1.7154x; 1.0748x over previous
#include <cuda_runtime.h>

#define BB 256
#define PP 1000
#define UU 768
#define EE 128
#define LOG2E 1.4426950408889634f
typedef unsigned long long u64;

// Folded weights. Ck/bk pre-scaled by LOG2E so exp(k) == ex2(k2).
__device__ float g_Ck[3][EE], g_bk[EE];
__device__ float g_Cv[3][EE], g_bv[EE];
__device__ float g_Cq[3][EE], g_bq[EE], g_wql[EE];

__device__ __forceinline__ float ex2(float x) {
    float r; asm("ex2.approx.f32 %0, %1;" : "=f"(r) : "f"(x)); return r;
}
__device__ __forceinline__ u64 fma2(u64 a, u64 b, u64 c) {
    u64 r; asm("fma.rn.f32x2 %0, %1, %2, %3;" : "=l"(r) : "l"(a), "l"(b), "l"(c)); return r;
}
__device__ __forceinline__ u64 add2(u64 a, u64 b) {
    u64 r; asm("add.rn.f32x2 %0, %1, %2;" : "=l"(r) : "l"(a), "l"(b)); return r;
}
__device__ __forceinline__ u64 pack2(float lo, float hi) {
    u64 r; asm("mov.b64 %0, {%1, %2};" : "=l"(r) : "f"(lo), "f"(hi)); return r;
}
__device__ __forceinline__ void unpack2(u64 v, float& lo, float& hi) {
    asm("mov.b64 {%0, %1}, %2;" : "=f"(lo), "=f"(hi) : "l"(v));
}
__device__ __forceinline__ void lds_v2u64(unsigned addr, u64& a, u64& b) {
    asm("ld.shared.v2.u64 {%0, %1}, [%2];" : "=l"(a), "=l"(b) : "r"(addr));
}

// 3 blocks (m = k/v/q), 128 threads: thread e folds column e of matrix m.
// W_embed rows + b_embed staged in smem -> 1 coalesced LDG + 4 LDS + 4 FMA per j.
__global__ __launch_bounds__(EE)
void precompute_kernel(const float* __restrict__ W_embed,
                       const float* __restrict__ b_embed,
                       const float* __restrict__ Wq,
                       const float* __restrict__ Wk,
                       const float* __restrict__ Wv) {
    __shared__ float sw[4 * EE];
    const int m = blockIdx.x;
    const int e = threadIdx.x;
    const float* M = (m == 0) ? Wk : (m == 1) ? Wv : Wq;
    sw[e] = W_embed[e];
    sw[EE + e] = W_embed[EE + e];
    sw[2 * EE + e] = W_embed[2 * EE + e];
    sw[3 * EE + e] = b_embed[e];
    __syncthreads();
    float a0 = 0.f, a1 = 0.f, a2 = 0.f, a3 = 0.f;
#pragma unroll 8
    for (int j = 0; j < EE; j++) {
        float wm = M[j * EE + e];
        a0 = fmaf(sw[j], wm, a0);
        a1 = fmaf(sw[EE + j], wm, a1);
        a2 = fmaf(sw[2 * EE + j], wm, a2);
        a3 = fmaf(sw[3 * EE + j], wm, a3);
    }
    if (m == 0) {
        g_Ck[0][e] = a0 * LOG2E; g_Ck[1][e] = a1 * LOG2E;
        g_Ck[2][e] = a2 * LOG2E; g_bk[e] = a3 * LOG2E;
    } else if (m == 1) {
        g_Cv[0][e] = a0; g_Cv[1][e] = a1; g_Cv[2][e] = a2; g_bv[e] = a3;
    } else {
        g_Cq[0][e] = a0; g_Cq[1][e] = a1; g_Cq[2][e] = a2; g_bq[e] = a3;
        g_wql[e] = Wq[EE * EE + e];
    }
}

// SMEM float-offset map (one pool; probs overlays pairA/pairB after phase 2)
#define OFF_PA   0              // pairA[384]: {x2p, x2p+1, y2p, y2p+1}  (1536 f)
#define OFF_PB   1536           // pairB[384]: {d2p, d2p+1, lw2p, lw2p+1}(1536 f)
#define OFF_PROBS 0             // probs[1001] overlay (pairA/B dead by then)
#define OFF_BIAS 3072           // 768
#define OFF_NF   3840           // 768
#define OFF_TS   4608           // 768
#define OFF_IDX  5376           // 768 (int)
#define OFF_PART 6144           // 3 quarters x 4 comps x 128 = 1536
#define OFF_RED  7680           // 16
#define OFF_REDI 7696           // 16
#define OFF_PW   7712           // 16
#define OFF_CN   7728           // 3
#define OFF_A    7732           // 4
#define OFF_MX   7736
#define OFF_SUM  7737
#define OFF_AMAX 7738
#define SMEM_F   7744

__global__ __launch_bounds__(512, 2)
void cvrp_main_kernel(const float* __restrict__ depot_xy,
                      const float* __restrict__ node_xy,
                      const float* __restrict__ node_demand,
                      const float* __restrict__ load_in,
                      const float* __restrict__ cur_dist,
                      const float* __restrict__ ninf_mask,
                      const float* __restrict__ log_scale,
                      const float* __restrict__ W_embed,
                      const float* __restrict__ b_embed,
                      const float* __restrict__ alpha_attn,
                      const float* __restrict__ alpha_com,
                      const int* __restrict__ current_node,
                      const int* __restrict__ uvi,
                      float* __restrict__ out) {
    __shared__ __align__(16) float SMf[SMEM_F];
    int* SMi = (int*)SMf;

    const int b = blockIdx.x;
    const int tid = threadIdx.x;
    const int lane = tid & 31;
    const int wid = tid >> 5;

    const float ls = log_scale[0];
    const float lsaa2 = -ls * alpha_attn[0] * LOG2E;
    const float lsac = -ls * alpha_com[0];
    const float loadb = load_in[b];

    if (tid == 0) {
        int cn = current_node[b];
        if (cn == 0) {
            float2 dp = ((const float2*)depot_xy)[b];
            SMf[OFF_CN] = dp.x; SMf[OFF_CN + 1] = dp.y; SMf[OFF_CN + 2] = 0.f;
        } else {
            int o = b * PP + (cn - 1);
            float2 xy = ((const float2*)node_xy)[o];
            SMf[OFF_CN] = xy.x; SMf[OFF_CN + 1] = xy.y; SMf[OFF_CN + 2] = node_demand[o];
        }
    }

    // Gather staged features into pair layout.
    for (int u = tid; u < UU; u += 512) {
        int idx = uvi[b * UU + u];
        SMi[OFF_IDX + u] = idx;
        float x, y, d;
        if (idx == 0) {
            float2 dp = ((const float2*)depot_xy)[b];
            x = dp.x; y = dp.y; d = 0.f;
        } else {
            int o = b * PP + (idx - 1);
            float2 xy = ((const float2*)node_xy)[o];
            x = xy.x; y = xy.y; d = node_demand[o];
        }
        float dist = cur_dist[b * UU + u];
        float nf = ninf_mask[b * UU + u];
        int p4 = (u >> 1) * 4 + (u & 1);
        SMf[OFF_PA + p4] = x;  SMf[OFF_PA + p4 + 2] = y;
        SMf[OFF_PB + p4] = d;  SMf[OFF_PB + p4 + 2] = fmaf(lsaa2, dist, nf * LOG2E);
        SMf[OFF_BIAS + u] = lsac * dist;
        SMf[OFF_NF + u] = nf;
    }
    __syncthreads();

    // sigmoid(q[e]) for e-threads (kept live through phase 1).
    const int e = tid & (EE - 1);
    const int q = tid >> 7;
    float sig = 0.f;
    if (tid < EE) {
        float qv = fmaf(SMf[OFF_CN], g_Cq[0][e],
                   fmaf(SMf[OFF_CN + 1], g_Cq[1][e],
                   fmaf(SMf[OFF_CN + 2], g_Cq[2][e], g_bq[e])))
                 + loadb * g_wql[e];
        sig = 1.f / (1.f + ex2(-qv * LOG2E));
    }

    // Phase 1: packed f32x2, 2 u's per iteration, accumulate S,Sx,Sy,Sd.
    const u64 ck0p = pack2(g_Ck[0][e], g_Ck[0][e]);
    const u64 ck1p = pack2(g_Ck[1][e], g_Ck[1][e]);
    const u64 ck2p = pack2(g_Ck[2][e], g_Ck[2][e]);
    const u64 bkp  = pack2(g_bk[e], g_bk[e]);
    u64 S2 = 0ull, Sx2 = 0ull, Sy2 = 0ull, Sd2 = 0ull;

    unsigned sbase = (unsigned)__cvta_generic_to_shared(SMf);
    unsigned addrA = sbase + (OFF_PA + q * (UU / 4) * 2) * 4;  // q*96 pairs * 16B
#pragma unroll 4
    for (int it = 0; it < UU / 8; it++, addrA += 16) {
        u64 xx, yy, dd, ll;
        lds_v2u64(addrA, xx, yy);
        lds_v2u64(addrA + OFF_PB * 4, dd, ll);
        u64 kk = add2(fma2(xx, ck0p, fma2(yy, ck1p, fma2(dd, ck2p, bkp))), ll);
        float klo, khi;
        unpack2(kk, klo, khi);
        u64 tt = pack2(ex2(klo), ex2(khi));
        S2  = add2(S2, tt);
        Sx2 = fma2(tt, xx, Sx2);
        Sy2 = fma2(tt, yy, Sy2);
        Sd2 = fma2(tt, dd, Sd2);
    }
    float lo, hi;
    unpack2(S2, lo, hi);  float den = lo + hi;
    unpack2(Sx2, lo, hi); float sxs = lo + hi;
    unpack2(Sy2, lo, hi); float sys = lo + hi;
    unpack2(Sd2, lo, hi); float sds = lo + hi;
    if (q) {
        int base = OFF_PART + (q - 1) * 4 * EE + e;
        SMf[base] = den; SMf[base + EE] = sxs;
        SMf[base + 2 * EE] = sys; SMf[base + 3 * EE] = sds;
    }
    __syncthreads();

    // e-threads: combine quarters, finalize num/den, aafm, folded A scalars.
    float p0 = 0.f, p1 = 0.f, p2 = 0.f, p3 = 0.f;
    if (tid < EE) {
#pragma unroll
        for (int c = 0; c < 3; c++) {
            int base = OFF_PART + c * 4 * EE + e;
            den += SMf[base]; sxs += SMf[base + EE];
            sys += SMf[base + 2 * EE]; sds += SMf[base + 3 * EE];
        }
        float num = fmaf(g_Cv[0][e], sxs, fmaf(g_Cv[1][e], sys,
                    fmaf(g_Cv[2][e], sds, g_bv[e] * den)));
        float aafm = sig * (num / den);
        p0 = aafm * W_embed[e];
        p1 = aafm * W_embed[EE + e];
        p2 = aafm * W_embed[2 * EE + e];
        p3 = aafm * b_embed[e];
#pragma unroll
        for (int o = 16; o; o >>= 1) {
            p0 += __shfl_xor_sync(0xffffffffu, p0, o);
            p1 += __shfl_xor_sync(0xffffffffu, p1, o);
            p2 += __shfl_xor_sync(0xffffffffu, p2, o);
            p3 += __shfl_xor_sync(0xffffffffu, p3, o);
        }
        if (lane == 0) {
            SMf[OFF_PW + wid * 4 + 0] = p0; SMf[OFF_PW + wid * 4 + 1] = p1;
            SMf[OFF_PW + wid * 4 + 2] = p2; SMf[OFF_PW + wid * 4 + 3] = p3;
        }
    }
    __syncthreads();
    if (tid < 4)
        SMf[OFF_A + tid] = SMf[OFF_PW + tid] + SMf[OFF_PW + 4 + tid]
                         + SMf[OFF_PW + 8 + tid] + SMf[OFF_PW + 12 + tid];
    __syncthreads();
    const float A0 = SMf[OFF_A], A1 = SMf[OFF_A + 1];
    const float A2 = SMf[OFF_A + 2], Ab = SMf[OFF_A + 3];

    // Phase 2 + inline max/argmax: logit2 = (10*tanh(score)+nf)*LOG2E.
    const float INV_SQRT_E = 0.08838834764831845f;
    float lm = -3.402823466e38f;
    int li = 0x7fffffff;
    for (int u = tid; u < UU; u += 512) {
        int p4 = (u >> 1) * 4 + (u & 1);
        float x = SMf[OFF_PA + p4], y = SMf[OFF_PA + p4 + 2];
        float d = SMf[OFF_PB + p4];
        float sc = fmaf(x, A0, fmaf(y, A1, fmaf(d, A2, Ab))) * INV_SQRT_E
                 + SMf[OFF_BIAS + u];
        float e2v = ex2(sc * (2.f * LOG2E));
        float th = 1.f - __fdividef(2.f, e2v + 1.f);
        float t = fmaf(10.f, th, SMf[OFF_NF + u]) * LOG2E;
        SMf[OFF_TS + u] = t;
        if (t > lm) { lm = t; li = u; }
    }
#pragma unroll
    for (int o = 16; o; o >>= 1) {
        float om = __shfl_xor_sync(0xffffffffu, lm, o);
        int oi = __shfl_xor_sync(0xffffffffu, li, o);
        if (om > lm || (om == lm && oi < li)) { lm = om; li = oi; }
    }
    if (lane == 0) { SMf[OFF_RED + wid] = lm; SMi[OFF_REDI + wid] = li; }
    __syncthreads();   // pairA/pairB now dead -> probs overlay becomes legal

    // Concurrently: warp 0 finishes max; everyone zeroes the probs row.
    if (tid < 32) {
        float m2 = (tid < 16) ? SMf[OFF_RED + tid] : -3.402823466e38f;
        int mi2 = (tid < 16) ? SMi[OFF_REDI + tid] : 0x7fffffff;
#pragma unroll
        for (int o = 8; o; o >>= 1) {
            float om = __shfl_xor_sync(0xffffffffu, m2, o);
            int oi = __shfl_xor_sync(0xffffffffu, mi2, o);
            if (om > m2 || (om == m2 && oi < mi2)) { m2 = om; mi2 = oi; }
        }
        if (tid == 0) { SMf[OFF_MX] = m2; SMi[OFF_AMAX] = mi2; }
    }
    for (int j = tid; j < PP + 1; j += 512) SMf[OFF_PROBS + j] = 0.f;
    __syncthreads();
    const float mx = SMf[OFF_MX];

    // Softmax sum; store exp values back into ts.
    float lsum = 0.f;
    for (int u = tid; u < UU; u += 512) {
        float p = ex2(SMf[OFF_TS + u] - mx);
        SMf[OFF_TS + u] = p;
        lsum += p;
    }
#pragma unroll
    for (int o = 16; o; o >>= 1) lsum += __shfl_xor_sync(0xffffffffu, lsum, o);
    if (lane == 0) SMf[OFF_RED + wid] = lsum;
    __syncthreads();
    if (tid < 32) {
        float v = (tid < 16) ? SMf[OFF_RED + tid] : 0.f;
#pragma unroll
        for (int o = 8; o; o >>= 1) v += __shfl_xor_sync(0xffffffffu, v, o);
        if (tid == 0) SMf[OFF_SUM] = v;
    }
    __syncthreads();
    const float inv = 1.f / SMf[OFF_SUM];

    // Scatter in smem (distinct sidx -> no conflicts), then coalesced store.
    for (int u = tid; u < UU; u += 512)
        SMf[OFF_PROBS + SMi[OFF_IDX + u]] = SMf[OFF_TS + u] * inv;
    __syncthreads();
    for (int j = tid; j < PP + 1; j += 512)
        out[b * (PP + 1) + j] = SMf[OFF_PROBS + j];
    if (tid == 0) {
        int amax = SMi[OFF_AMAX];
        out[BB * (PP + 1) + b] = (float)SMi[OFF_IDX + amax];
        out[BB * (PP + 1) + BB + b] = SMf[OFF_TS + amax] * inv;
    }
}

extern "C" void kernel_launch(void* const* d_in, const int* in_sizes, int n_in,
                              void* d_out, int out_size) {
    (void)in_sizes; (void)n_in; (void)out_size;
    const float* depot_xy    = (const float*)d_in[0];
    const float* node_xy     = (const float*)d_in[1];
    const float* node_demand = (const float*)d_in[2];
    const float* load_in     = (const float*)d_in[3];
    const float* cur_dist    = (const float*)d_in[4];
    const float* ninf_mask   = (const float*)d_in[5];
    const float* log_scale   = (const float*)d_in[6];
    const float* W_embed     = (const float*)d_in[7];
    const float* b_embed     = (const float*)d_in[8];
    const float* Wq          = (const float*)d_in[9];
    const float* Wk          = (const float*)d_in[10];
    const float* Wv          = (const float*)d_in[11];
    const float* alpha_attn  = (const float*)d_in[12];
    const float* alpha_com   = (const float*)d_in[13];
    const int*   current_node = (const int*)d_in[14];
    const int*   uvi          = (const int*)d_in[15];
    float* out = (float*)d_out;

    precompute_kernel<<<3, EE>>>(W_embed, b_embed, Wq, Wk, Wv);
    cvrp_main_kernel<<<BB, 512>>>(depot_xy, node_xy, node_demand, load_in,
                                  cur_dist, ninf_mask, log_scale, W_embed,
                                  b_embed, alpha_attn, alpha_com,
                                  current_node, uvi, out);
}

// round 4
// speedup vs baseline: 2.8783x; 1.6779x over previous
#include <cuda_runtime.h>

#define BB 256
#define PP 1000
#define UU 768
#define EE 128
#define LOG2E 1.4426950408889634f

// Folded weights (natural-log space). Ck = W_embed@Wk etc.
__device__ float g_Ck[3][EE];
__device__ float g_Cv[3][EE], g_bv[EE];
__device__ float g_Cq[3][EE], g_bq[EE], g_wql[EE];

__device__ __forceinline__ float ex2(float x) {
    float r; asm("ex2.approx.f32 %0, %1;" : "=f"(r) : "f"(x)); return r;
}

// m -> (i,j,l) canonical order (i outer, then j, then l), i+j+l <= 4.
__constant__ unsigned char c_map[35][3] = {
    {0,0,0},{0,0,1},{0,0,2},{0,0,3},{0,0,4},
    {0,1,0},{0,1,1},{0,1,2},{0,1,3},
    {0,2,0},{0,2,1},{0,2,2},
    {0,3,0},{0,3,1},
    {0,4,0},
    {1,0,0},{1,0,1},{1,0,2},{1,0,3},
    {1,1,0},{1,1,1},{1,1,2},
    {1,2,0},{1,2,1},
    {1,3,0},
    {2,0,0},{2,0,1},{2,0,2},
    {2,1,0},{2,1,1},
    {2,2,0},
    {3,0,0},{3,0,1},
    {3,1,0},
    {4,0,0}
};

// 3 blocks (m = k/v/q), 128 threads: thread e folds column e of matrix m.
__global__ __launch_bounds__(EE)
void precompute_kernel(const float* __restrict__ W_embed,
                       const float* __restrict__ b_embed,
                       const float* __restrict__ Wq,
                       const float* __restrict__ Wk,
                       const float* __restrict__ Wv) {
    __shared__ float sw[4 * EE];
    const int m = blockIdx.x;
    const int e = threadIdx.x;
    const float* M = (m == 0) ? Wk : (m == 1) ? Wv : Wq;
    sw[e] = W_embed[e];
    sw[EE + e] = W_embed[EE + e];
    sw[2 * EE + e] = W_embed[2 * EE + e];
    sw[3 * EE + e] = b_embed[e];
    __syncthreads();
    float a0 = 0.f, a1 = 0.f, a2 = 0.f, a3 = 0.f;
#pragma unroll 8
    for (int j = 0; j < EE; j++) {
        float wm = M[j * EE + e];
        a0 = fmaf(sw[j], wm, a0);
        a1 = fmaf(sw[EE + j], wm, a1);
        a2 = fmaf(sw[2 * EE + j], wm, a2);
        a3 = fmaf(sw[3 * EE + j], wm, a3);
    }
    if (m == 0) {
        g_Ck[0][e] = a0; g_Ck[1][e] = a1; g_Ck[2][e] = a2;  // bk cancels in num/den
    } else if (m == 1) {
        g_Cv[0][e] = a0; g_Cv[1][e] = a1; g_Cv[2][e] = a2; g_bv[e] = a3;
    } else {
        g_Cq[0][e] = a0; g_Cq[1][e] = a1; g_Cq[2][e] = a2; g_bq[e] = a3;
        g_wql[e] = Wq[EE * EE + e];
    }
}

// SMEM float-offset map (probs overlays x/y after phase 2)
#define OFF_X    0              // 768
#define OFF_Y    768            // 768
#define OFF_PROBS 0             // 1001 overlay (x,y dead by then)
#define OFF_D    1536           // 768
#define OFF_W    2304           // 768
#define OFF_BIAS 3072           // 768
#define OFF_NF   3840           // 768
#define OFF_TS   4608           // 768
#define OFF_IDX  5376           // 768 (int)
#define OFF_PART 6144           // 35*4
#define OFF_M3   6284           // 5*5*5
#define OFF_RED  6412           // 16
#define OFF_REDI 6428           // 16
#define OFF_PW   6444           // 16
#define OFF_CN   6460           // 3
#define OFF_A    6464           // 4
#define OFF_MX   6468
#define OFF_SUM  6469
#define OFF_AMAX 6470
#define SMEM_F   6476
#define M3(i,j,l) SMf[OFF_M3 + ((i)*5 + (j))*5 + (l)]

__global__ __launch_bounds__(512, 2)
void cvrp_main_kernel(const float* __restrict__ depot_xy,
                      const float* __restrict__ node_xy,
                      const float* __restrict__ node_demand,
                      const float* __restrict__ load_in,
                      const float* __restrict__ cur_dist,
                      const float* __restrict__ ninf_mask,
                      const float* __restrict__ log_scale,
                      const float* __restrict__ W_embed,
                      const float* __restrict__ b_embed,
                      const float* __restrict__ alpha_attn,
                      const float* __restrict__ alpha_com,
                      const int* __restrict__ current_node,
                      const int* __restrict__ uvi,
                      float* __restrict__ out) {
    __shared__ __align__(16) float SMf[SMEM_F];
    int* SMi = (int*)SMf;

    const int b = blockIdx.x;
    const int tid = threadIdx.x;
    const int lane = tid & 31;
    const int wid = tid >> 5;

    const float ls = log_scale[0];
    const float lsaa2 = -ls * alpha_attn[0] * LOG2E;  // log2-space attn bias
    const float lsac = -ls * alpha_com[0];            // natural com bias
    const float loadb = load_in[b];

    if (tid == 0) {
        int cn = current_node[b];
        if (cn == 0) {
            float2 dp = ((const float2*)depot_xy)[b];
            SMf[OFF_CN] = dp.x; SMf[OFF_CN + 1] = dp.y; SMf[OFF_CN + 2] = 0.f;
        } else {
            int o = b * PP + (cn - 1);
            float2 xy = ((const float2*)node_xy)[o];
            SMf[OFF_CN] = xy.x; SMf[OFF_CN + 1] = xy.y; SMf[OFF_CN + 2] = node_demand[o];
        }
    }

    // Gather staged features (does NOT need folded weights -> overlaps PDL).
    for (int u = tid; u < UU; u += 512) {
        int idx = uvi[b * UU + u];
        SMi[OFF_IDX + u] = idx;
        float x, y, d;
        if (idx == 0) {
            float2 dp = ((const float2*)depot_xy)[b];
            x = dp.x; y = dp.y; d = 0.f;
        } else {
            int o = b * PP + (idx - 1);
            float2 xy = ((const float2*)node_xy)[o];
            x = xy.x; y = xy.y; d = node_demand[o];
        }
        float dist = cur_dist[b * UU + u];
        float nf = ninf_mask[b * UU + u];
        SMf[OFF_X + u] = x; SMf[OFF_Y + u] = y; SMf[OFF_D + u] = d;
        SMf[OFF_W + u] = ex2(fmaf(lsaa2, dist, nf * LOG2E));  // w = exp(attn bias)
        SMf[OFF_BIAS + u] = lsac * dist;
        SMf[OFF_NF + u] = nf;
    }

    // Wait for precompute_kernel (PDL programmatic dependency).
    cudaGridDependencySynchronize();
    __syncthreads();

    // ---- Warps 8-11 (tid 256..383): per-e Taylor powers + sigmoid(q) ----
    float pa0=1.f, pa1=0.f, pa2=0.f, pa3=0.f;
    float pb0=1.f, pb1=0.f, pb2=0.f, pb3=0.f;
    float pc0=1.f, pc1=0.f, pc2=0.f, pc3=0.f;
    float sig = 0.f;
    const int e = tid - 256;
    if (tid >= 256 && tid < 384) {
        float a = g_Ck[0][e], bcoef = g_Ck[1][e], c = g_Ck[2][e];
        pa1 = a;     pa2 = a * a * 0.5f;          pa3 = pa2 * a * (1.f / 3.f);
        pb1 = bcoef; pb2 = bcoef * bcoef * 0.5f;  pb3 = pb2 * bcoef * (1.f / 3.f);
        pc1 = c;     pc2 = c * c * 0.5f;          pc3 = pc2 * c * (1.f / 3.f);
        float qv = fmaf(SMf[OFF_CN], g_Cq[0][e],
                   fmaf(SMf[OFF_CN + 1], g_Cq[1][e],
                   fmaf(SMf[OFF_CN + 2], g_Cq[2][e], g_bq[e])))
                 + loadb * g_wql[e];
        sig = 1.f / (1.f + ex2(-qv * LOG2E));
    }

    // ---- Warps 0-3 (tid < 128): weighted moments M_ijl, i+j+l <= 4 ----
    if (tid < 128) {
        float acc[35];
#pragma unroll
        for (int m = 0; m < 35; m++) acc[m] = 0.f;
        const int u0 = wid * 192 + lane;
#pragma unroll 2
        for (int k = 0; k < 6; k++) {
            int u = u0 + 32 * k;
            float x = SMf[OFF_X + u], y = SMf[OFF_Y + u];
            float d = SMf[OFF_D + u], w = SMf[OFF_W + u];
            float px[5], py[5], pd[5];
            px[0]=1.f; px[1]=x; px[2]=x*x; px[3]=px[2]*x; px[4]=px[2]*px[2];
            py[0]=1.f; py[1]=y; py[2]=y*y; py[3]=py[2]*y; py[4]=py[2]*py[2];
            pd[0]=1.f; pd[1]=d; pd[2]=d*d; pd[3]=pd[2]*d; pd[4]=pd[2]*pd[2];
            int m = 0;
#pragma unroll
            for (int i = 0; i <= 4; i++) {
                float wx = w * px[i];
#pragma unroll
                for (int j = 0; j <= 4 - i; j++) {
                    float wxy = wx * py[j];
#pragma unroll
                    for (int l = 0; l <= 4 - i - j; l++) {
                        acc[m] = fmaf(wxy, pd[l], acc[m]);
                        m++;
                    }
                }
            }
        }
#pragma unroll
        for (int m = 0; m < 35; m++) {
            float v = acc[m];
#pragma unroll
            for (int o = 16; o; o >>= 1) v += __shfl_xor_sync(0xffffffffu, v, o);
            if (lane == 0) SMf[OFF_PART + m * 4 + wid] = v;
        }
    }
    __syncthreads();

    // Combine partials into M3 (threads 384..418, idle warps 12-13).
    if (tid >= 384 && tid < 384 + 35) {
        int m = tid - 384;
        float s = SMf[OFF_PART + m * 4] + SMf[OFF_PART + m * 4 + 1]
                + SMf[OFF_PART + m * 4 + 2] + SMf[OFF_PART + m * 4 + 3];
        M3(c_map[m][0], c_map[m][1], c_map[m][2]) = s;
    }
    __syncthreads();

    // ---- Warps 8-11: evaluate S0,Sx,Sy,Sd -> aafm_e -> folded A partials ----
    float p0 = 0.f, p1 = 0.f, p2 = 0.f, p3 = 0.f;
    if (tid >= 256 && tid < 384) {
        float pa[4] = {pa0, pa1, pa2, pa3};
        float pb[4] = {pb0, pb1, pb2, pb3};
        float pc[4] = {pc0, pc1, pc2, pc3};
        float S0 = 0.f, Sx = 0.f, Sy = 0.f, Sd = 0.f;
#pragma unroll
        for (int i = 0; i <= 3; i++)
#pragma unroll
            for (int j = 0; j <= 3 - i; j++)
#pragma unroll
                for (int l = 0; l <= 3 - i - j; l++) {
                    float t = pa[i] * pb[j] * pc[l];
                    S0 = fmaf(t, M3(i, j, l), S0);
                    Sx = fmaf(t, M3(i + 1, j, l), Sx);
                    Sy = fmaf(t, M3(i, j + 1, l), Sy);
                    Sd = fmaf(t, M3(i, j, l + 1), Sd);
                }
        float num = fmaf(g_Cv[0][e], Sx, fmaf(g_Cv[1][e], Sy,
                    fmaf(g_Cv[2][e], Sd, g_bv[e] * S0)));
        float aafm = sig * (num / S0);
        p0 = aafm * W_embed[e];
        p1 = aafm * W_embed[EE + e];
        p2 = aafm * W_embed[2 * EE + e];
        p3 = aafm * b_embed[e];
#pragma unroll
        for (int o = 16; o; o >>= 1) {
            p0 += __shfl_xor_sync(0xffffffffu, p0, o);
            p1 += __shfl_xor_sync(0xffffffffu, p1, o);
            p2 += __shfl_xor_sync(0xffffffffu, p2, o);
            p3 += __shfl_xor_sync(0xffffffffu, p3, o);
        }
        if (lane == 0) {
            int w8 = wid - 8;
            SMf[OFF_PW + w8 * 4 + 0] = p0; SMf[OFF_PW + w8 * 4 + 1] = p1;
            SMf[OFF_PW + w8 * 4 + 2] = p2; SMf[OFF_PW + w8 * 4 + 3] = p3;
        }
    }
    __syncthreads();
    if (tid < 4)
        SMf[OFF_A + tid] = SMf[OFF_PW + tid] + SMf[OFF_PW + 4 + tid]
                         + SMf[OFF_PW + 8 + tid] + SMf[OFF_PW + 12 + tid];
    __syncthreads();
    const float A0 = SMf[OFF_A], A1 = SMf[OFF_A + 1];
    const float A2 = SMf[OFF_A + 2], Ab = SMf[OFF_A + 3];

    // Phase 2 + inline max/argmax: logit2 = (10*tanh(score)+nf)*LOG2E.
    const float INV_SQRT_E = 0.08838834764831845f;
    float lm = -3.402823466e38f;
    int li = 0x7fffffff;
    for (int u = tid; u < UU; u += 512) {
        float sc = fmaf(SMf[OFF_X + u], A0, fmaf(SMf[OFF_Y + u], A1,
                   fmaf(SMf[OFF_D + u], A2, Ab))) * INV_SQRT_E
                 + SMf[OFF_BIAS + u];
        float e2v = ex2(sc * (2.f * LOG2E));
        float th = 1.f - __fdividef(2.f, e2v + 1.f);
        float t = fmaf(10.f, th, SMf[OFF_NF + u]) * LOG2E;
        SMf[OFF_TS + u] = t;
        if (t > lm) { lm = t; li = u; }
    }
#pragma unroll
    for (int o = 16; o; o >>= 1) {
        float om = __shfl_xor_sync(0xffffffffu, lm, o);
        int oi = __shfl_xor_sync(0xffffffffu, li, o);
        if (om > lm || (om == lm && oi < li)) { lm = om; li = oi; }
    }
    if (lane == 0) { SMf[OFF_RED + wid] = lm; SMi[OFF_REDI + wid] = li; }
    __syncthreads();   // x/y now dead -> probs overlay legal

    if (tid < 32) {
        float m2 = (tid < 16) ? SMf[OFF_RED + tid] : -3.402823466e38f;
        int mi2 = (tid < 16) ? SMi[OFF_REDI + tid] : 0x7fffffff;
#pragma unroll
        for (int o = 8; o; o >>= 1) {
            float om = __shfl_xor_sync(0xffffffffu, m2, o);
            int oi = __shfl_xor_sync(0xffffffffu, mi2, o);
            if (om > m2 || (om == m2 && oi < mi2)) { m2 = om; mi2 = oi; }
        }
        if (tid == 0) { SMf[OFF_MX] = m2; SMi[OFF_AMAX] = mi2; }
    }
    for (int j = tid; j < PP + 1; j += 512) SMf[OFF_PROBS + j] = 0.f;
    __syncthreads();
    const float mx = SMf[OFF_MX];

    float lsum = 0.f;
    for (int u = tid; u < UU; u += 512) {
        float p = ex2(SMf[OFF_TS + u] - mx);
        SMf[OFF_TS + u] = p;
        lsum += p;
    }
#pragma unroll
    for (int o = 16; o; o >>= 1) lsum += __shfl_xor_sync(0xffffffffu, lsum, o);
    if (lane == 0) SMf[OFF_RED + wid] = lsum;
    __syncthreads();
    if (tid < 32) {
        float v = (tid < 16) ? SMf[OFF_RED + tid] : 0.f;
#pragma unroll
        for (int o = 8; o; o >>= 1) v += __shfl_xor_sync(0xffffffffu, v, o);
        if (tid == 0) SMf[OFF_SUM] = v;
    }
    __syncthreads();
    const float inv = 1.f / SMf[OFF_SUM];

    for (int u = tid; u < UU; u += 512)
        SMf[OFF_PROBS + SMi[OFF_IDX + u]] = SMf[OFF_TS + u] * inv;
    __syncthreads();
    for (int j = tid; j < PP + 1; j += 512)
        out[b * (PP + 1) + j] = SMf[OFF_PROBS + j];
    if (tid == 0) {
        int amax = SMi[OFF_AMAX];
        out[BB * (PP + 1) + b] = (float)SMi[OFF_IDX + amax];
        out[BB * (PP + 1) + BB + b] = SMf[OFF_TS + amax] * inv;
    }
}

extern "C" void kernel_launch(void* const* d_in, const int* in_sizes, int n_in,
                              void* d_out, int out_size) {
    (void)in_sizes; (void)n_in; (void)out_size;
    const float* depot_xy    = (const float*)d_in[0];
    const float* node_xy     = (const float*)d_in[1];
    const float* node_demand = (const float*)d_in[2];
    const float* load_in     = (const float*)d_in[3];
    const float* cur_dist    = (const float*)d_in[4];
    const float* ninf_mask   = (const float*)d_in[5];
    const float* log_scale   = (const float*)d_in[6];
    const float* W_embed     = (const float*)d_in[7];
    const float* b_embed     = (const float*)d_in[8];
    const float* Wq          = (const float*)d_in[9];
    const float* Wk          = (const float*)d_in[10];
    const float* Wv          = (const float*)d_in[11];
    const float* alpha_attn  = (const float*)d_in[12];
    const float* alpha_com   = (const float*)d_in[13];
    const int*   current_node = (const int*)d_in[14];
    const int*   uvi          = (const int*)d_in[15];
    float* out = (float*)d_out;

    precompute_kernel<<<3, EE>>>(W_embed, b_embed, Wq, Wk, Wv);

    // Main kernel with programmatic dependent launch: it starts while
    // precompute drains; cudaGridDependencySynchronize() inside gates the
    // first read of g_* (gather overlaps the dependency).
    cudaLaunchConfig_t cfg = {};
    cfg.gridDim = dim3(BB, 1, 1);
    cfg.blockDim = dim3(512, 1, 1);
    cfg.dynamicSmemBytes = 0;
    cfg.stream = 0;
    cudaLaunchAttribute attrs[1];
    attrs[0].id = cudaLaunchAttributeProgrammaticStreamSerialization;
    attrs[0].val.programmaticStreamSerializationAllowed = 1;
    cfg.attrs = attrs;
    cfg.numAttrs = 1;
    cudaLaunchKernelEx(&cfg, cvrp_main_kernel,
                       depot_xy, node_xy, node_demand, load_in, cur_dist,
                       ninf_mask, log_scale, W_embed, b_embed, alpha_attn,
                       alpha_com, current_node, uvi, out);
}

// round 5
// speedup vs baseline: 4.0341x; 1.4016x over previous
#include <cuda_runtime.h>

#define BB 256
#define PP 1000
#define UU 768
#define EE 128
#define LOG2E 1.4426950408889634f

// Folded weights (natural-log space). Ck = W_embed@Wk etc. (bk cancels).
__device__ float g_Ck[3][EE];
__device__ float g_Cv[3][EE], g_bv[EE];
__device__ float g_Cq[3][EE], g_bq[EE], g_wql[EE];

__device__ __forceinline__ float ex2(float x) {
    float r; asm("ex2.approx.f32 %0, %1;" : "=f"(r) : "f"(x)); return r;
}

// Canonical index of moment (i,j,l), i+j+l <= 3, i-major then j then l.
__device__ __forceinline__ constexpr int IDX3(int i, int j, int l) {
    int bi = (i == 0) ? 0 : (i == 1) ? 10 : (i == 2) ? 16 : 19;
    int bj = j * (4 - i) - (j * (j - 1)) / 2;
    return bi + bj + l;
}

// 3 blocks (m = k/v/q), 512 threads: e = tid&127, j split 4 ways.
__global__ __launch_bounds__(512)
void precompute_kernel(const float* __restrict__ W_embed,
                       const float* __restrict__ b_embed,
                       const float* __restrict__ Wq,
                       const float* __restrict__ Wk,
                       const float* __restrict__ Wv) {
    __shared__ float sw[4 * EE];
    __shared__ float part[4][4][EE];
    const int m = blockIdx.x;
    const int tid = threadIdx.x;
    const int e = tid & (EE - 1);
    const int jc = tid >> 7;
    const float* M = (m == 0) ? Wk : (m == 1) ? Wv : Wq;
    sw[tid] = (tid < 3 * EE) ? W_embed[tid] : b_embed[tid - 3 * EE];
    __syncthreads();
    float a0 = 0.f, a1 = 0.f, a2 = 0.f, a3 = 0.f;
    const int j0 = jc * 32;
#pragma unroll 8
    for (int j = j0; j < j0 + 32; j++) {
        float wm = M[j * EE + e];
        a0 = fmaf(sw[j], wm, a0);
        a1 = fmaf(sw[EE + j], wm, a1);
        a2 = fmaf(sw[2 * EE + j], wm, a2);
        a3 = fmaf(sw[3 * EE + j], wm, a3);
    }
    part[jc][0][e] = a0; part[jc][1][e] = a1;
    part[jc][2][e] = a2; part[jc][3][e] = a3;
    __syncthreads();
    if (tid < EE) {
        float s0 = part[0][0][e] + part[1][0][e] + part[2][0][e] + part[3][0][e];
        float s1 = part[0][1][e] + part[1][1][e] + part[2][1][e] + part[3][1][e];
        float s2 = part[0][2][e] + part[1][2][e] + part[2][2][e] + part[3][2][e];
        float s3 = part[0][3][e] + part[1][3][e] + part[2][3][e] + part[3][3][e];
        if (m == 0) {
            g_Ck[0][e] = s0; g_Ck[1][e] = s1; g_Ck[2][e] = s2;
        } else if (m == 1) {
            g_Cv[0][e] = s0; g_Cv[1][e] = s1; g_Cv[2][e] = s2; g_bv[e] = s3;
        } else {
            g_Cq[0][e] = s0; g_Cq[1][e] = s1; g_Cq[2][e] = s2; g_bq[e] = s3;
            g_wql[e] = Wq[EE * EE + e];
        }
    }
}

// SMEM float-offset map (probs overlays x/y after phase 2).
#define OFF_X    0              // 768
#define OFF_Y    768            // 768
#define OFF_PROBS 0             // 1001 overlay (x,y dead by then)
#define OFF_D    1536           // 768
#define OFF_W    2304           // 768
#define OFF_BIAS 3072           // 768
#define OFF_NF   3840           // 768
#define OFF_TS   4608           // 768 (holds p = ex2(logit2))
#define OFF_IDX  5376           // 768 (int)
#define OFF_PART 6144           // 4 warps x 20 moments = 80 (16B aligned)
#define OFF_PW   6224           // 16
#define OFF_RED  6240           // 8
#define OFF_REDM 6248           // 8
#define OFF_REDI 6256           // 8 (int)
#define OFF_CN   6264           // 3
#define OFF_SUM  6267
#define OFF_AMAX 6268           // int
#define SMEM_F   6272

__global__ __launch_bounds__(256, 4)
void cvrp_main_kernel(const float* __restrict__ depot_xy,
                      const float* __restrict__ node_xy,
                      const float* __restrict__ node_demand,
                      const float* __restrict__ load_in,
                      const float* __restrict__ cur_dist,
                      const float* __restrict__ ninf_mask,
                      const float* __restrict__ log_scale,
                      const float* __restrict__ W_embed,
                      const float* __restrict__ b_embed,
                      const float* __restrict__ alpha_attn,
                      const float* __restrict__ alpha_com,
                      const int* __restrict__ current_node,
                      const int* __restrict__ uvi,
                      float* __restrict__ out) {
    __shared__ __align__(16) float SMf[SMEM_F];
    int* SMi = (int*)SMf;

    const int b = blockIdx.x;
    const int tid = threadIdx.x;
    const int lane = tid & 31;
    const int wid = tid >> 5;

    const float ls = log_scale[0];
    const float lsaa2 = -ls * alpha_attn[0] * LOG2E;
    const float lsac = -ls * alpha_com[0];
    const float loadb = load_in[b];

    if (tid == 0) {
        int cn = current_node[b];
        if (cn == 0) {
            float2 dp = ((const float2*)depot_xy)[b];
            SMf[OFF_CN] = dp.x; SMf[OFF_CN + 1] = dp.y; SMf[OFF_CN + 2] = 0.f;
        } else {
            int o = b * PP + (cn - 1);
            float2 xy = ((const float2*)node_xy)[o];
            SMf[OFF_CN] = xy.x; SMf[OFF_CN + 1] = xy.y; SMf[OFF_CN + 2] = node_demand[o];
        }
    }

    // Gather (needs no folded weights -> overlaps PDL dependency).
#pragma unroll
    for (int u = tid; u < UU; u += 256) {
        int idx = uvi[b * UU + u];
        SMi[OFF_IDX + u] = idx;
        float x, y, d;
        if (idx == 0) {
            float2 dp = ((const float2*)depot_xy)[b];
            x = dp.x; y = dp.y; d = 0.f;
        } else {
            int o = b * PP + (idx - 1);
            float2 xy = ((const float2*)node_xy)[o];
            x = xy.x; y = xy.y; d = node_demand[o];
        }
        float dist = cur_dist[b * UU + u];
        float nf = ninf_mask[b * UU + u];
        SMf[OFF_X + u] = x; SMf[OFF_Y + u] = y; SMf[OFF_D + u] = d;
        SMf[OFF_W + u] = ex2(fmaf(lsaa2, dist, nf * LOG2E));
        SMf[OFF_BIAS + u] = lsac * dist;
        SMf[OFF_NF + u] = nf;
    }

    cudaGridDependencySynchronize();
    __syncthreads();   // (1)

    // ---- Warps 4-7 (tid 128..255): Taylor coefficient powers + sigmoid ----
    float pa[3] = {1.f, 0.f, 0.f}, pb[3] = {1.f, 0.f, 0.f}, pc[3] = {1.f, 0.f, 0.f};
    float sig = 0.f;
    const int e = tid - 128;
    if (tid >= 128) {
        float a = g_Ck[0][e], bc = g_Ck[1][e], cc = g_Ck[2][e];
        pa[1] = a;  pa[2] = a * a * 0.5f;
        pb[1] = bc; pb[2] = bc * bc * 0.5f;
        pc[1] = cc; pc[2] = cc * cc * 0.5f;
        float qv = fmaf(SMf[OFF_CN], g_Cq[0][e],
                   fmaf(SMf[OFF_CN + 1], g_Cq[1][e],
                   fmaf(SMf[OFF_CN + 2], g_Cq[2][e], g_bq[e])))
                 + loadb * g_wql[e];
        sig = 1.f / (1.f + ex2(-qv * LOG2E));
    }

    // ---- Warps 0-3 (tid < 128): 20 weighted moments, i+j+l <= 3 ----
    if (tid < 128) {
        float acc[20];
#pragma unroll
        for (int m = 0; m < 20; m++) acc[m] = 0.f;
        const int u0 = wid * 192 + lane;
#pragma unroll
        for (int k = 0; k < 6; k++) {
            int u = u0 + 32 * k;
            float x = SMf[OFF_X + u], y = SMf[OFF_Y + u];
            float d = SMf[OFF_D + u], w = SMf[OFF_W + u];
            float px[4] = {1.f, x, x * x, x * x * x};
            float py[4] = {1.f, y, y * y, y * y * y};
            float pd[4] = {1.f, d, d * d, d * d * d};
            int m = 0;
#pragma unroll
            for (int i = 0; i <= 3; i++) {
                float wx = w * px[i];
#pragma unroll
                for (int j = 0; j <= 3 - i; j++) {
                    float wxy = wx * py[j];
#pragma unroll
                    for (int l = 0; l <= 3 - i - j; l++) {
                        acc[m] = fmaf(wxy, pd[l], acc[m]);
                        m++;
                    }
                }
            }
        }
#pragma unroll
        for (int m = 0; m < 20; m++) {
#pragma unroll
            for (int o = 16; o; o >>= 1)
                acc[m] += __shfl_xor_sync(0xffffffffu, acc[m], o);
        }
        if (lane == 0) {
            float4* dst = (float4*)&SMf[OFF_PART + wid * 20];
            dst[0] = make_float4(acc[0], acc[1], acc[2], acc[3]);
            dst[1] = make_float4(acc[4], acc[5], acc[6], acc[7]);
            dst[2] = make_float4(acc[8], acc[9], acc[10], acc[11]);
            dst[3] = make_float4(acc[12], acc[13], acc[14], acc[15]);
            dst[4] = make_float4(acc[16], acc[17], acc[18], acc[19]);
        }
    }
    __syncthreads();   // (2)

    // ---- Warps 4-7: combine partials inline, evaluate, fold to A partials ----
    if (tid >= 128) {
        float M[20];
#pragma unroll
        for (int m = 0; m < 20; m++)
            M[m] = SMf[OFF_PART + m] + SMf[OFF_PART + 20 + m]
                 + SMf[OFF_PART + 40 + m] + SMf[OFF_PART + 60 + m];
        float S0 = 0.f, Sx = 0.f, Sy = 0.f, Sd = 0.f;
#pragma unroll
        for (int i = 0; i <= 2; i++)
#pragma unroll
            for (int j = 0; j <= 2 - i; j++)
#pragma unroll
                for (int l = 0; l <= 2 - i - j; l++) {
                    float t = pa[i] * pb[j] * pc[l];
                    S0 = fmaf(t, M[IDX3(i, j, l)], S0);
                    Sx = fmaf(t, M[IDX3(i + 1, j, l)], Sx);
                    Sy = fmaf(t, M[IDX3(i, j + 1, l)], Sy);
                    Sd = fmaf(t, M[IDX3(i, j, l + 1)], Sd);
                }
        float num = fmaf(g_Cv[0][e], Sx, fmaf(g_Cv[1][e], Sy,
                    fmaf(g_Cv[2][e], Sd, g_bv[e] * S0)));
        float aafm = sig * (num / S0);
        float p0 = aafm * W_embed[e];
        float p1 = aafm * W_embed[EE + e];
        float p2 = aafm * W_embed[2 * EE + e];
        float p3 = aafm * b_embed[e];
#pragma unroll
        for (int o = 16; o; o >>= 1) {
            p0 += __shfl_xor_sync(0xffffffffu, p0, o);
            p1 += __shfl_xor_sync(0xffffffffu, p1, o);
            p2 += __shfl_xor_sync(0xffffffffu, p2, o);
            p3 += __shfl_xor_sync(0xffffffffu, p3, o);
        }
        if (lane == 0) {
            int w4 = wid - 4;
            SMf[OFF_PW + w4 * 4 + 0] = p0; SMf[OFF_PW + w4 * 4 + 1] = p1;
            SMf[OFF_PW + w4 * 4 + 2] = p2; SMf[OFF_PW + w4 * 4 + 3] = p3;
        }
    }
    __syncthreads();   // (3)

    // Every thread forms A itself (16 broadcast LDS, no extra barrier).
    const float A0 = SMf[OFF_PW + 0] + SMf[OFF_PW + 4] + SMf[OFF_PW + 8] + SMf[OFF_PW + 12];
    const float A1 = SMf[OFF_PW + 1] + SMf[OFF_PW + 5] + SMf[OFF_PW + 9] + SMf[OFF_PW + 13];
    const float A2 = SMf[OFF_PW + 2] + SMf[OFF_PW + 6] + SMf[OFF_PW + 10] + SMf[OFF_PW + 14];
    const float Ab = SMf[OFF_PW + 3] + SMf[OFF_PW + 7] + SMf[OFF_PW + 11] + SMf[OFF_PW + 15];

    // Phase 2 fused with softmax-sum + argmax (no max subtraction: |logit|<=10).
    const float INV_SQRT_E = 0.08838834764831845f;
    float lsum = 0.f, pm = -1.f;
    int pi = 0x7fffffff;
#pragma unroll
    for (int u = tid; u < UU; u += 256) {
        float sc = fmaf(SMf[OFF_X + u], A0, fmaf(SMf[OFF_Y + u], A1,
                   fmaf(SMf[OFF_D + u], A2, Ab))) * INV_SQRT_E
                 + SMf[OFF_BIAS + u];
        float e2v = ex2(sc * (2.f * LOG2E));
        float th = 1.f - __fdividef(2.f, e2v + 1.f);
        float p = ex2(fmaf(10.f, th, SMf[OFF_NF + u]) * LOG2E);
        SMf[OFF_TS + u] = p;
        lsum += p;
        if (p > pm) { pm = p; pi = u; }   // ascending u -> first occurrence
    }
#pragma unroll
    for (int o = 16; o; o >>= 1) {
        lsum += __shfl_xor_sync(0xffffffffu, lsum, o);
        float om = __shfl_xor_sync(0xffffffffu, pm, o);
        int oi = __shfl_xor_sync(0xffffffffu, pi, o);
        if (om > pm || (om == pm && oi < pi)) { pm = om; pi = oi; }
    }
    if (lane == 0) {
        SMf[OFF_RED + wid] = lsum; SMf[OFF_REDM + wid] = pm; SMi[OFF_REDI + wid] = pi;
    }
    __syncthreads();   // (4)  x/y dead -> probs overlay legal

    if (tid < 32) {
        float v = (tid < 8) ? SMf[OFF_RED + tid] : 0.f;
        float m2 = (tid < 8) ? SMf[OFF_REDM + tid] : -1.f;
        int mi2 = (tid < 8) ? SMi[OFF_REDI + tid] : 0x7fffffff;
#pragma unroll
        for (int o = 4; o; o >>= 1) {
            v += __shfl_xor_sync(0xffffffffu, v, o);
            float om = __shfl_xor_sync(0xffffffffu, m2, o);
            int oi = __shfl_xor_sync(0xffffffffu, mi2, o);
            if (om > m2 || (om == m2 && oi < mi2)) { m2 = om; mi2 = oi; }
        }
        if (tid == 0) { SMf[OFF_SUM] = v; SMi[OFF_AMAX] = mi2; }
    }
#pragma unroll
    for (int j = tid; j < PP + 1; j += 256) SMf[OFF_PROBS + j] = 0.f;
    __syncthreads();   // (5)

    const float inv = 1.f / SMf[OFF_SUM];
#pragma unroll
    for (int u = tid; u < UU; u += 256)
        SMf[OFF_PROBS + SMi[OFF_IDX + u]] = SMf[OFF_TS + u] * inv;
    __syncthreads();   // (6)

#pragma unroll
    for (int j = tid; j < PP + 1; j += 256)
        out[b * (PP + 1) + j] = SMf[OFF_PROBS + j];
    if (tid == 0) {
        int amax = SMi[OFF_AMAX];
        out[BB * (PP + 1) + b] = (float)SMi[OFF_IDX + amax];
        out[BB * (PP + 1) + BB + b] = SMf[OFF_TS + amax] * inv;
    }
}

extern "C" void kernel_launch(void* const* d_in, const int* in_sizes, int n_in,
                              void* d_out, int out_size) {
    (void)in_sizes; (void)n_in; (void)out_size;
    const float* depot_xy    = (const float*)d_in[0];
    const float* node_xy     = (const float*)d_in[1];
    const float* node_demand = (const float*)d_in[2];
    const float* load_in     = (const float*)d_in[3];
    const float* cur_dist    = (const float*)d_in[4];
    const float* ninf_mask   = (const float*)d_in[5];
    const float* log_scale   = (const float*)d_in[6];
    const float* W_embed     = (const float*)d_in[7];
    const float* b_embed     = (const float*)d_in[8];
    const float* Wq          = (const float*)d_in[9];
    const float* Wk          = (const float*)d_in[10];
    const float* Wv          = (const float*)d_in[11];
    const float* alpha_attn  = (const float*)d_in[12];
    const float* alpha_com   = (const float*)d_in[13];
    const int*   current_node = (const int*)d_in[14];
    const int*   uvi          = (const int*)d_in[15];
    float* out = (float*)d_out;

    precompute_kernel<<<3, 512>>>(W_embed, b_embed, Wq, Wk, Wv);

    // PDL: main starts while precompute drains; gather runs before the
    // dependency gate, first g_* read comes after it.
    cudaLaunchConfig_t cfg = {};
    cfg.gridDim = dim3(BB, 1, 1);
    cfg.blockDim = dim3(256, 1, 1);
    cfg.dynamicSmemBytes = 0;
    cfg.stream = 0;
    cudaLaunchAttribute attrs[1];
    attrs[0].id = cudaLaunchAttributeProgrammaticStreamSerialization;
    attrs[0].val.programmaticStreamSerializationAllowed = 1;
    cfg.attrs = attrs;
    cfg.numAttrs = 1;
    cudaLaunchKernelEx(&cfg, cvrp_main_kernel,
                       depot_xy, node_xy, node_demand, load_in, cur_dist,
                       ninf_mask, log_scale, W_embed, b_embed, alpha_attn,
                       alpha_com, current_node, uvi, out);
}